// round 2
// baseline (speedup 1.0000x reference)
#include <cuda_runtime.h>
#include <cstdint>

#define N_NODES 50000
#define N_EDGES 800000

// ---------------- scratch (device globals; no allocation allowed) ----------
__device__ float g_buf1[(size_t)N_NODES * 256];  // xw, then g (post-agg layer 2 input)
__device__ float g_buf2[(size_t)N_NODES * 256];  // h (post-relu layer 1 output)
__device__ float g_wc[256 * 256];                // [W_mu | W_ls] fused
__device__ float g_bc[256];                      // [b_mu | b_ls] fused
__device__ int   g_deg[N_NODES];
__device__ float g_dinv[N_NODES];
__device__ int   g_cnt[N_NODES];                 // real (non-self) in-degree
__device__ int   g_off[N_NODES];                 // CSR row offsets (exclusive scan of cnt)
__device__ int   g_cur[N_NODES];                 // fill cursors
__device__ int   g_csr[N_EDGES];                 // src per incoming edge, bucketed by dst

// ---------------- preprocessing kernels ------------------------------------
__global__ void k_init_deg(int n) {
    int i = blockIdx.x * blockDim.x + threadIdx.x;
    if (i < n) g_deg[i] = 1;  // self loop
}

// edge_index is int32 (JAX default x64-disabled downcasts int64 -> int32)
__global__ void k_hist(const int* __restrict__ ei, int e_cnt, int n) {
    int e = blockIdx.x * blockDim.x + threadIdx.x;
    if (e < e_cnt) {
        int d = ei[e_cnt + e];  // dst row of edge_index
        if ((unsigned)d < (unsigned)n) atomicAdd(&g_deg[d], 1);
    }
}

__global__ void k_finalize_deg(int n) {
    int i = blockIdx.x * blockDim.x + threadIdx.x;
    if (i < n) {
        int dg = g_deg[i];
        g_dinv[i] = rsqrtf((float)dg);
        g_cnt[i] = dg - 1;
    }
}

// single-block exclusive scan of g_cnt -> g_off, g_cur (n ~ 50k, 49 chunks)
__global__ void k_scan(int n) {
    __shared__ int wsum[32];
    __shared__ int carry;
    int tid = threadIdx.x;
    int lane = tid & 31, warp = tid >> 5;
    if (tid == 0) carry = 0;
    __syncthreads();
    for (int base = 0; base < n; base += 1024) {
        int i = base + tid;
        int v = (i < n) ? g_cnt[i] : 0;
        int x = v;
        #pragma unroll
        for (int dstep = 1; dstep < 32; dstep <<= 1) {
            int y = __shfl_up_sync(0xffffffffu, x, dstep);
            if (lane >= dstep) x += y;
        }
        if (lane == 31) wsum[warp] = x;
        __syncthreads();
        if (warp == 0) {
            int w = wsum[lane];
            #pragma unroll
            for (int dstep = 1; dstep < 32; dstep <<= 1) {
                int y = __shfl_up_sync(0xffffffffu, w, dstep);
                if (lane >= dstep) w += y;
            }
            wsum[lane] = w;
        }
        __syncthreads();
        int woff = (warp > 0) ? wsum[warp - 1] : 0;
        int excl = carry + woff + x - v;
        if (i < n) { g_off[i] = excl; g_cur[i] = excl; }
        int total = wsum[31];
        __syncthreads();
        if (tid == 0) carry += total;
        __syncthreads();
    }
}

__global__ void k_fill(const int* __restrict__ ei, int e_cnt, int n) {
    int e = blockIdx.x * blockDim.x + threadIdx.x;
    if (e < e_cnt) {
        int s = ei[e];
        int d = ei[e_cnt + e];
        if ((unsigned)d < (unsigned)n && (unsigned)s < (unsigned)n) {
            int pos = atomicAdd(&g_cur[d], 1);
            if ((unsigned)pos < (unsigned)N_EDGES) g_csr[pos] = s;
        }
    }
}

__global__ void k_prep_wc(const float* __restrict__ Wmu, const float* __restrict__ Wls,
                          const float* __restrict__ bmu, const float* __restrict__ bls) {
    int i = blockIdx.x * blockDim.x + threadIdx.x;
    if (i < 256 * 256) {
        int k = i >> 8, c = i & 255;
        g_wc[i] = (c < 128) ? Wmu[k * 128 + c] : Wls[k * 128 + (c - 128)];
    }
    if (i < 256) g_bc[i] = (i < 128) ? bmu[i] : bls[i - 128];
}

// ---------------- SGEMM: 128x128x16 tile, 8x8 per thread, N fixed 256 ------
// PHASE 1: C = A(x) @ B(W1) -> g_buf1 (plain write)
// PHASE 2: C = g_buf1 @ g_wc; epilogue writes split [2,M,128] + fused bias
template<int PHASE, int K>
__global__ void __launch_bounds__(256, 2) k_sgemm(const float* __restrict__ Aext,
                                                  const float* __restrict__ Bext,
                                                  float* __restrict__ outext, int M) {
    const float* __restrict__ A = (PHASE == 1) ? Aext : g_buf1;
    const float* __restrict__ B = (PHASE == 1) ? Bext : g_wc;

    __shared__ float As[16][128];
    __shared__ float Bs[16][128];

    int t = threadIdx.x;
    int m0 = blockIdx.x * 128;
    int n0 = blockIdx.y * 128;
    int tx = t & 15, ty = t >> 4;

    float acc[8][8];
    #pragma unroll
    for (int i = 0; i < 8; i++)
        #pragma unroll
        for (int j = 0; j < 8; j++) acc[i][j] = 0.f;

    const float4* A4 = (const float4*)A;
    const float4* B4 = (const float4*)B;

    for (int kt = 0; kt < K; kt += 16) {
        // A tile: 128 rows x 16 k, stored transposed As[k][m]
        #pragma unroll
        for (int r = 0; r < 2; r++) {
            int row = r * 64 + (t >> 2);
            int col4 = (t & 3);
            float4 v = make_float4(0.f, 0.f, 0.f, 0.f);
            int gm = m0 + row;
            if (gm < M) v = A4[((size_t)gm * K + kt) / 4 + col4];
            As[col4 * 4 + 0][row] = v.x;
            As[col4 * 4 + 1][row] = v.y;
            As[col4 * 4 + 2][row] = v.z;
            As[col4 * 4 + 3][row] = v.w;
        }
        // B tile: 16 k x 128 n
        #pragma unroll
        for (int r = 0; r < 2; r++) {
            int idx = r * 256 + t;
            int row = idx >> 5;
            int col4 = idx & 31;
            float4 v = B4[((kt + row) * 256 + n0) / 4 + col4];
            *(float4*)&Bs[row][col4 * 4] = v;
        }
        __syncthreads();
        #pragma unroll
        for (int k = 0; k < 16; k++) {
            float a[8], b[8];
            #pragma unroll
            for (int i = 0; i < 8; i++) a[i] = As[k][ty * 8 + i];
            #pragma unroll
            for (int j = 0; j < 8; j++) b[j] = Bs[k][tx * 8 + j];
            #pragma unroll
            for (int i = 0; i < 8; i++)
                #pragma unroll
                for (int j = 0; j < 8; j++) acc[i][j] += a[i] * b[j];
        }
        __syncthreads();
    }

    if (PHASE == 1) {
        #pragma unroll
        for (int i = 0; i < 8; i++) {
            int m = m0 + ty * 8 + i;
            if (m < M) {
                #pragma unroll
                for (int j = 0; j < 8; j += 4) {
                    int n = n0 + tx * 8 + j;
                    float4 v = make_float4(acc[i][j], acc[i][j + 1], acc[i][j + 2], acc[i][j + 3]);
                    *(float4*)&g_buf1[(size_t)m * 256 + n] = v;
                }
            }
        }
    } else {
        float bsv[8];
        #pragma unroll
        for (int j = 0; j < 8; j++) bsv[j] = g_bc[n0 + tx * 8 + j];
        int nbase = n0 + tx * 8;
        int half = nbase >> 7;          // column block stays within one half (8 | 128)
        int cbase = nbase & 127;
        #pragma unroll
        for (int i = 0; i < 8; i++) {
            int m = m0 + ty * 8 + i;
            if (m < M) {
                float* orow = outext + ((size_t)half * M + m) * 128 + cbase;
                #pragma unroll
                for (int j = 0; j < 8; j++) orow[j] = acc[i][j] + bsv[j];
            }
        }
    }
}

// ---------------- aggregation: gather-style, one CTA (64 thr) per node -----
// out[d] = dinv[d] * ( dinv[d]*in[d] + sum_{s in csr(d)} dinv[s]*in[s] )  [+bias, relu]
template<int PASS>
__global__ void k_agg(const float* __restrict__ bias, int M) {
    int d = blockIdx.x;
    if (d >= M) return;
    const float4* __restrict__ F = (const float4*)(PASS == 1 ? g_buf1 : g_buf2);
    float4* __restrict__ O = (float4*)(PASS == 1 ? g_buf2 : g_buf1);
    int c = threadIdx.x;  // 0..63, each handles one float4 of the 256-wide row
    float wd = g_dinv[d];
    float4 v = F[(size_t)d * 64 + c];
    float4 acc = make_float4(wd * v.x, wd * v.y, wd * v.z, wd * v.w);
    int b = g_off[d];
    int n = g_cnt[d];
    for (int i = 0; i < n; i++) {
        int s = g_csr[b + i];
        float w = g_dinv[s];
        float4 u = F[(size_t)s * 64 + c];
        acc.x += w * u.x;
        acc.y += w * u.y;
        acc.z += w * u.z;
        acc.w += w * u.w;
    }
    acc.x *= wd; acc.y *= wd; acc.z *= wd; acc.w *= wd;
    if (PASS == 1) {
        float4 bb = ((const float4*)bias)[c];
        acc.x = fmaxf(acc.x + bb.x, 0.f);
        acc.y = fmaxf(acc.y + bb.y, 0.f);
        acc.z = fmaxf(acc.z + bb.z, 0.f);
        acc.w = fmaxf(acc.w + bb.w, 0.f);
    }
    O[(size_t)d * 64 + c] = acc;
}

// ---------------- launch ----------------------------------------------------
extern "C" void kernel_launch(void* const* d_in, const int* in_sizes, int n_in,
                              void* d_out, int out_size) {
    const float* x   = (const float*)d_in[0];
    const int*   ei  = (const int*)d_in[1];
    const float* W1  = (const float*)d_in[2];
    const float* b1  = (const float*)d_in[3];
    const float* Wmu = (const float*)d_in[4];
    const float* bmu = (const float*)d_in[5];
    const float* Wls = (const float*)d_in[6];
    const float* bls = (const float*)d_in[7];
    float* out = (float*)d_out;

    int N = in_sizes[0] / 512;   // 50000
    int E = in_sizes[1] / 2;     // 800000

    k_init_deg<<<(N + 255) / 256, 256>>>(N);
    k_prep_wc<<<(256 * 256 + 255) / 256, 256>>>(Wmu, Wls, bmu, bls);
    k_hist<<<(E + 255) / 256, 256>>>(ei, E, N);
    k_finalize_deg<<<(N + 255) / 256, 256>>>(N);
    k_scan<<<1, 1024>>>(N);
    k_fill<<<(E + 255) / 256, 256>>>(ei, E, N);

    // layer 1: xw = x @ W1 ; h = relu(dinv * Agg(dinv * xw) + b1)
    k_sgemm<1, 512><<<dim3((N + 127) / 128, 2), 256>>>(x, W1, nullptr, N);
    k_agg<1><<<N, 64>>>(b1, N);

    // layer 2: g = dinv * Agg(dinv * h) ; [mu|logstd] = g @ [Wmu|Wls] + [bmu|bls]
    k_agg<2><<<N, 64>>>(nullptr, N);
    k_sgemm<2, 256><<<dim3((N + 127) / 128, 2), 256>>>(nullptr, nullptr, out, N);
}

// round 4
// speedup vs baseline: 2.4891x; 2.4891x over previous
#include <cuda_runtime.h>
#include <cuda_bf16.h>
#include <cstdint>

#define N_NODES 50000
#define N_EDGES 800000

// ---------------- scratch (device globals; no allocation allowed) ----------
__device__ float g_buf1[(size_t)N_NODES * 256];   // xw (GEMM1 out), agg1 input
__device__ float g_buf2[(size_t)N_NODES * 256];   // h (post-relu), agg2 input
__device__ __nv_bfloat16 g_x_hi[(size_t)N_NODES * 512];
__device__ __nv_bfloat16 g_x_lo[(size_t)N_NODES * 512];
__device__ __nv_bfloat16 g_g_hi[(size_t)N_NODES * 256];  // agg2 output split
__device__ __nv_bfloat16 g_g_lo[(size_t)N_NODES * 256];
__device__ __nv_bfloat16 g_w1t_hi[256 * 512];     // W1^T  [n,k]
__device__ __nv_bfloat16 g_w1t_lo[256 * 512];
__device__ __nv_bfloat16 g_wct_hi[256 * 256];     // [Wmu|Wls]^T  [n,k]
__device__ __nv_bfloat16 g_wct_lo[256 * 256];
__device__ float g_bc[256];                       // [b_mu | b_ls]
__device__ int   g_deg[N_NODES];
__device__ float g_dinv[N_NODES];
__device__ int   g_cnt[N_NODES];
__device__ int   g_off[N_NODES];
__device__ int   g_cur[N_NODES];
__device__ int   g_csr[N_EDGES];

// ---------------- helpers ----------------------------------------------------
__device__ __forceinline__ uint32_t smem_u32(const void* p) {
    uint32_t a;
    asm("{ .reg .u64 t; cvta.to.shared.u64 t, %1; cvt.u32.u64 %0, t; }" : "=r"(a) : "l"(p));
    return a;
}
__device__ __forceinline__ void ldsm_x4(uint32_t addr, uint32_t* r) {
    asm volatile("ldmatrix.sync.aligned.m8n8.x4.shared.b16 {%0,%1,%2,%3}, [%4];"
        : "=r"(r[0]), "=r"(r[1]), "=r"(r[2]), "=r"(r[3]) : "r"(addr));
}
__device__ __forceinline__ void mma16816(float* c, const uint32_t* a, const uint32_t* b) {
    asm volatile(
        "mma.sync.aligned.m16n8k16.row.col.f32.bf16.bf16.f32 "
        "{%0,%1,%2,%3}, {%4,%5,%6,%7}, {%8,%9}, {%0,%1,%2,%3};"
        : "+f"(c[0]), "+f"(c[1]), "+f"(c[2]), "+f"(c[3])
        : "r"(a[0]), "r"(a[1]), "r"(a[2]), "r"(a[3]), "r"(b[0]), "r"(b[1]));
}
__device__ __forceinline__ void split_bf16(float v, __nv_bfloat16& h, __nv_bfloat16& l) {
    h = __float2bfloat16(v);
    l = __float2bfloat16(v - __bfloat162float(h));
}

// ---------------- preprocessing kernels ------------------------------------
__global__ void k_init_deg(int n) {
    int i = blockIdx.x * blockDim.x + threadIdx.x;
    if (i < n) g_deg[i] = 1;
}
__global__ void k_hist(const int* __restrict__ ei, int e_cnt, int n) {
    int e = blockIdx.x * blockDim.x + threadIdx.x;
    if (e < e_cnt) {
        int d = ei[e_cnt + e];
        if ((unsigned)d < (unsigned)n) atomicAdd(&g_deg[d], 1);
    }
}
__global__ void k_finalize_deg(int n) {
    int i = blockIdx.x * blockDim.x + threadIdx.x;
    if (i < n) {
        int dg = g_deg[i];
        g_dinv[i] = rsqrtf((float)dg);
        g_cnt[i] = dg - 1;
    }
}
__global__ void k_scan(int n) {
    __shared__ int wsum[32];
    __shared__ int carry;
    int tid = threadIdx.x, lane = tid & 31, warp = tid >> 5;
    if (tid == 0) carry = 0;
    __syncthreads();
    for (int base = 0; base < n; base += 1024) {
        int i = base + tid;
        int v = (i < n) ? g_cnt[i] : 0;
        int x = v;
        #pragma unroll
        for (int s = 1; s < 32; s <<= 1) {
            int y = __shfl_up_sync(0xffffffffu, x, s);
            if (lane >= s) x += y;
        }
        if (lane == 31) wsum[warp] = x;
        __syncthreads();
        if (warp == 0) {
            int w = wsum[lane];
            #pragma unroll
            for (int s = 1; s < 32; s <<= 1) {
                int y = __shfl_up_sync(0xffffffffu, w, s);
                if (lane >= s) w += y;
            }
            wsum[lane] = w;
        }
        __syncthreads();
        int woff = (warp > 0) ? wsum[warp - 1] : 0;
        if (i < n) { g_off[i] = carry + woff + x - v; g_cur[i] = g_off[i]; }
        int total = wsum[31];
        __syncthreads();
        if (tid == 0) carry += total;
        __syncthreads();
    }
}
__global__ void k_fill(const int* __restrict__ ei, int e_cnt, int n) {
    int e = blockIdx.x * blockDim.x + threadIdx.x;
    if (e < e_cnt) {
        int s = ei[e];
        int d = ei[e_cnt + e];
        if ((unsigned)d < (unsigned)n && (unsigned)s < (unsigned)n) {
            int pos = atomicAdd(&g_cur[d], 1);
            if ((unsigned)pos < (unsigned)N_EDGES) g_csr[pos] = s;
        }
    }
}

// x [M,512] fp32 -> hi/lo bf16
__global__ void k_conv_x(const float* __restrict__ x, long n4) {
    long i = (long)blockIdx.x * blockDim.x + threadIdx.x;
    if (i >= n4) return;
    float4 v = ((const float4*)x)[i];
    __nv_bfloat16 h0, h1, h2, h3, l0, l1, l2, l3;
    split_bf16(v.x, h0, l0); split_bf16(v.y, h1, l1);
    split_bf16(v.z, h2, l2); split_bf16(v.w, h3, l3);
    __nv_bfloat162 ha = __halves2bfloat162(h0, h1), hb = __halves2bfloat162(h2, h3);
    __nv_bfloat162 la = __halves2bfloat162(l0, l1), lb = __halves2bfloat162(l2, l3);
    ((uint2*)g_x_hi)[i] = make_uint2(*(uint32_t*)&ha, *(uint32_t*)&hb);
    ((uint2*)g_x_lo)[i] = make_uint2(*(uint32_t*)&la, *(uint32_t*)&lb);
}
// W1 [512,256] -> W1^T hi/lo [256,512]
__global__ void k_prep_w1t(const float* __restrict__ W1) {
    int i = blockIdx.x * blockDim.x + threadIdx.x;
    if (i >= 256 * 512) return;
    int n = i >> 9, k = i & 511;
    __nv_bfloat16 h, l;
    split_bf16(W1[k * 256 + n], h, l);
    g_w1t_hi[i] = h; g_w1t_lo[i] = l;
}
// [Wmu|Wls] -> Wc^T hi/lo [256,256], plus fused bias
__global__ void k_prep_wct(const float* __restrict__ Wmu, const float* __restrict__ Wls,
                           const float* __restrict__ bmu, const float* __restrict__ bls) {
    int i = blockIdx.x * blockDim.x + threadIdx.x;
    if (i >= 256 * 256) return;
    int n = i >> 8, k = i & 255;
    float v = (n < 128) ? Wmu[k * 128 + n] : Wls[k * 128 + (n - 128)];
    __nv_bfloat16 h, l;
    split_bf16(v, h, l);
    g_wct_hi[i] = h; g_wct_lo[i] = l;
    if (i < 256) g_bc[i] = (i < 128) ? bmu[i] : bls[i - 128];
}

// ---------------- mma.sync GEMM: C[M,256] = A[M,K] @ B^T, split-bf16 --------
// CTA tile 128m x 64n x 32k; 8 warps of 32m x 32n; 3 products Ah*Bh+Ah*Bl+Al*Bh.
// SMEM rows padded to 40 bf16 (80B stride) => conflict-free ldmatrix.
// PHASE 1: A=x hi/lo (K=512), B=W1^T -> g_buf1 fp32
// PHASE 2: A=g hi/lo (K=256), B=Wc^T -> out [2,M,128] + bias
template<int KTOT, int PHASE>
__global__ void __launch_bounds__(256, 2) k_gemm_mma(float* __restrict__ outp, int M) {
    constexpr int KT = KTOT / 32;
    const __nv_bfloat16* __restrict__ Ah = (PHASE == 1) ? g_x_hi : g_g_hi;
    const __nv_bfloat16* __restrict__ Al = (PHASE == 1) ? g_x_lo : g_g_lo;
    const __nv_bfloat16* __restrict__ Bh = (PHASE == 1) ? g_w1t_hi : g_wct_hi;
    const __nv_bfloat16* __restrict__ Bl = (PHASE == 1) ? g_w1t_lo : g_wct_lo;

    __shared__ uint16_t sAh[128 * 40], sAl[128 * 40];
    __shared__ uint16_t sBh[64 * 40],  sBl[64 * 40];

    int tid = threadIdx.x;
    int wid = tid >> 5, lane = tid & 31;
    int m0 = blockIdx.x * 128;
    int n0 = blockIdx.y * 64;

    // warp layout: 4 (m) x 2 (n); warp tile 32m x 32n
    int wm = (wid & 3) * 32;
    int wn = (wid >> 2) * 32;

    uint32_t sAh_b = smem_u32(sAh), sAl_b = smem_u32(sAl);
    uint32_t sBh_b = smem_u32(sBh), sBl_b = smem_u32(sBl);

    // ldmatrix lane addressing offsets
    int sub = lane >> 3, lr = lane & 7;
    // A: m = wm + lr + (sub&1)*8 (+mi*16), kc = ks + (sub>>1)*8
    uint32_t a_off = (uint32_t)((wm + lr + (sub & 1) * 8) * 80 + ((sub >> 1) * 8) * 2);
    // B: n = wn + lr + (sub>>1)*8 (+nb*16), kc = ks + (sub&1)*8
    uint32_t b_off = (uint32_t)((wn + lr + (sub >> 1) * 8) * 80 + ((sub & 1) * 8) * 2);

    float c[2][4][4];
    #pragma unroll
    for (int i = 0; i < 2; i++)
        #pragma unroll
        for (int j = 0; j < 4; j++)
            #pragma unroll
            for (int q = 0; q < 4; q++) c[i][j][q] = 0.f;

    const uint4* A4h = (const uint4*)Ah;
    const uint4* A4l = (const uint4*)Al;
    const uint4* B4h = (const uint4*)Bh;
    const uint4* B4l = (const uint4*)Bl;

    // prefetch registers: A 2 uint4 per hi/lo, B 1 uint4 per hi/lo
    uint4 pAh[2], pAl[2], pBh, pBl;
    int arow[2], achk[2];
    {
        #pragma unroll
        for (int it = 0; it < 2; it++) {
            int idx = it * 256 + tid;         // 512 uint4 over A tile
            arow[it] = idx >> 2; achk[it] = idx & 3;
        }
    }
    int brow = tid >> 2, bchk = tid & 3;

    auto ldg_tile = [&](int kt) {
        int ktk = kt * 32;
        #pragma unroll
        for (int it = 0; it < 2; it++) {
            int gm = m0 + arow[it];
            if (gm >= M) gm = M - 1;
            long gi = ((long)gm * KTOT + ktk) >> 3;
            pAh[it] = A4h[gi + achk[it]];
            pAl[it] = A4l[gi + achk[it]];
        }
        long gb = ((long)(n0 + brow) * KTOT + ktk) >> 3;
        pBh = B4h[gb + bchk];
        pBl = B4l[gb + bchk];
    };
    auto sts_tile = [&]() {
        #pragma unroll
        for (int it = 0; it < 2; it++) {
            uint32_t so = (uint32_t)(arow[it] * 80 + achk[it] * 16);
            *(uint4*)((char*)sAh + so) = pAh[it];
            *(uint4*)((char*)sAl + so) = pAl[it];
        }
        uint32_t sb = (uint32_t)(brow * 80 + bchk * 16);
        *(uint4*)((char*)sBh + sb) = pBh;
        *(uint4*)((char*)sBl + sb) = pBl;
    };

    ldg_tile(0);
    for (int kt = 0; kt < KT; kt++) {
        __syncthreads();   // smem free (prev tile consumed)
        sts_tile();
        __syncthreads();
        if (kt + 1 < KT) ldg_tile(kt + 1);   // overlap with mma

        #pragma unroll
        for (int ks = 0; ks < 2; ks++) {
            uint32_t koff = (uint32_t)(ks * 16 * 2);
            uint32_t ah[2][4], al[2][4], bh[2][4], bl[2][4];
            #pragma unroll
            for (int mi = 0; mi < 2; mi++) {
                ldsm_x4(sAh_b + a_off + mi * 16 * 80 + koff, ah[mi]);
                ldsm_x4(sAl_b + a_off + mi * 16 * 80 + koff, al[mi]);
            }
            #pragma unroll
            for (int nb = 0; nb < 2; nb++) {
                ldsm_x4(sBh_b + b_off + nb * 16 * 80 + koff, bh[nb]);
                ldsm_x4(sBl_b + b_off + nb * 16 * 80 + koff, bl[nb]);
            }
            #pragma unroll
            for (int mi = 0; mi < 2; mi++)
                #pragma unroll
                for (int nj = 0; nj < 4; nj++) {
                    uint32_t bfh[2] = { bh[nj >> 1][(nj & 1) * 2], bh[nj >> 1][(nj & 1) * 2 + 1] };
                    uint32_t bfl[2] = { bl[nj >> 1][(nj & 1) * 2], bl[nj >> 1][(nj & 1) * 2 + 1] };
                    mma16816(c[mi][nj], ah[mi], bfh);
                    mma16816(c[mi][nj], ah[mi], bfl);
                    mma16816(c[mi][nj], al[mi], bfh);
                }
        }
    }

    // epilogue
    int mrow = (lane >> 2);          // 0..7
    int ncol = (lane & 3) * 2;
    #pragma unroll
    for (int mi = 0; mi < 2; mi++) {
        #pragma unroll
        for (int nj = 0; nj < 4; nj++) {
            int n_g = n0 + wn + nj * 8 + ncol;
            #pragma unroll
            for (int h = 0; h < 2; h++) {
                int m_g = m0 + wm + mi * 16 + mrow + h * 8;
                if (m_g < M) {
                    float v0 = c[mi][nj][h * 2], v1 = c[mi][nj][h * 2 + 1];
                    if (PHASE == 1) {
                        *(float2*)&g_buf1[(size_t)m_g * 256 + n_g] = make_float2(v0, v1);
                    } else {
                        int half = n_g >> 7, cc = n_g & 127;
                        float2 o = make_float2(v0 + g_bc[n_g], v1 + g_bc[n_g + 1]);
                        *(float2*)&outp[((size_t)half * M + m_g) * 128 + cc] = o;
                    }
                }
            }
        }
    }
}

// ---------------- aggregation: gather-style, one CTA (64 thr) per node -----
// PASS 1: g_buf1 -> g_buf2, relu(. + b1)
// PASS 2: g_buf2 -> g_g_hi/g_g_lo (split bf16)
template<int PASS>
__global__ void k_agg(const float* __restrict__ bias, int M) {
    int d = blockIdx.x;
    if (d >= M) return;
    const float4* __restrict__ F = (const float4*)(PASS == 1 ? g_buf1 : g_buf2);
    int c = threadIdx.x;  // 0..63
    float wd = g_dinv[d];
    float4 v = F[(size_t)d * 64 + c];
    float4 acc = make_float4(wd * v.x, wd * v.y, wd * v.z, wd * v.w);
    int b = g_off[d];
    int n = g_cnt[d];
    for (int i = 0; i < n; i++) {
        int s = g_csr[b + i];
        float w = g_dinv[s];
        float4 u = F[(size_t)s * 64 + c];
        acc.x += w * u.x; acc.y += w * u.y; acc.z += w * u.z; acc.w += w * u.w;
    }
    acc.x *= wd; acc.y *= wd; acc.z *= wd; acc.w *= wd;
    if (PASS == 1) {
        float4 bb = ((const float4*)bias)[c];
        acc.x = fmaxf(acc.x + bb.x, 0.f);
        acc.y = fmaxf(acc.y + bb.y, 0.f);
        acc.z = fmaxf(acc.z + bb.z, 0.f);
        acc.w = fmaxf(acc.w + bb.w, 0.f);
        *(float4*)&g_buf2[(size_t)d * 256 + c * 4] = acc;
    } else {
        __nv_bfloat16 h0, h1, h2, h3, l0, l1, l2, l3;
        split_bf16(acc.x, h0, l0); split_bf16(acc.y, h1, l1);
        split_bf16(acc.z, h2, l2); split_bf16(acc.w, h3, l3);
        __nv_bfloat162 ha = __halves2bfloat162(h0, h1), hb = __halves2bfloat162(h2, h3);
        __nv_bfloat162 la = __halves2bfloat162(l0, l1), lb = __halves2bfloat162(l2, l3);
        ((uint2*)g_g_hi)[(size_t)d * 64 + c] = make_uint2(*(uint32_t*)&ha, *(uint32_t*)&hb);
        ((uint2*)g_g_lo)[(size_t)d * 64 + c] = make_uint2(*(uint32_t*)&la, *(uint32_t*)&lb);
    }
}

// ---------------- launch ----------------------------------------------------
extern "C" void kernel_launch(void* const* d_in, const int* in_sizes, int n_in,
                              void* d_out, int out_size) {
    const float* x   = (const float*)d_in[0];
    const int*   ei  = (const int*)d_in[1];
    const float* W1  = (const float*)d_in[2];
    const float* b1  = (const float*)d_in[3];
    const float* Wmu = (const float*)d_in[4];
    const float* bmu = (const float*)d_in[5];
    const float* Wls = (const float*)d_in[6];
    const float* bls = (const float*)d_in[7];
    float* out = (float*)d_out;

    int N = in_sizes[0] / 512;   // 50000
    int E = in_sizes[1] / 2;     // 800000

    // preprocessing (CSR + degrees) and weight/input conversion
    k_init_deg<<<(N + 255) / 256, 256>>>(N);
    k_prep_w1t<<<(256 * 512 + 255) / 256, 256>>>(W1);
    k_prep_wct<<<(256 * 256 + 255) / 256, 256>>>(Wmu, Wls, bmu, bls);
    k_hist<<<(E + 255) / 256, 256>>>(ei, E, N);
    k_finalize_deg<<<(N + 255) / 256, 256>>>(N);
    k_scan<<<1, 1024>>>(N);
    k_fill<<<(E + 255) / 256, 256>>>(ei, E, N);
    long n4 = (long)N * 512 / 4;
    k_conv_x<<<(int)((n4 + 255) / 256), 256>>>(x, n4);

    int mt = (N + 127) / 128;
    // layer 1: xw = x @ W1 (tensor cores); h = relu(dinv*Agg(dinv*xw) + b1)
    k_gemm_mma<512, 1><<<dim3(mt, 4), 256>>>(nullptr, N);
    k_agg<1><<<N, 64>>>(b1, N);
    // layer 2: g = dinv*Agg(dinv*h) (split-bf16 out); [mu|ls] = g @ Wc + bc
    k_agg<2><<<N, 64>>>(nullptr, N);
    k_gemm_mma<256, 2><<<dim3(mt, 4), 256>>>(out, N);
}

// round 5
// speedup vs baseline: 2.8350x; 1.1389x over previous
#include <cuda_runtime.h>
#include <cuda_bf16.h>
#include <cstdint>

#define N_NODES 50000
#define N_EDGES 800000

// ---------------- scratch (device globals; no allocation allowed) ----------
__device__ float g_buf1[(size_t)N_NODES * 256];   // xw (GEMM1 out), agg1 input
__device__ float g_buf2[(size_t)N_NODES * 256];   // h (post-relu), agg2 input
__device__ __nv_bfloat16 g_g_hi[(size_t)N_NODES * 256];  // agg2 output split
__device__ __nv_bfloat16 g_g_lo[(size_t)N_NODES * 256];
__device__ __nv_bfloat16 g_w1t_hi[256 * 512];     // W1^T  [n,k]
__device__ __nv_bfloat16 g_w1t_lo[256 * 512];
__device__ __nv_bfloat16 g_wct_hi[256 * 256];     // [Wmu|Wls]^T  [n,k]
__device__ __nv_bfloat16 g_wct_lo[256 * 256];
__device__ float g_bc[256];                       // [b_mu | b_ls]
__device__ int   g_deg[N_NODES];
__device__ float g_dinv[N_NODES];
__device__ int   g_cnt[N_NODES];
__device__ int   g_off[N_NODES];
__device__ int   g_cur[N_NODES];
__device__ int   g_csr[N_EDGES];

// ---------------- helpers ----------------------------------------------------
__device__ __forceinline__ uint32_t smem_u32(const void* p) {
    uint32_t a;
    asm("{ .reg .u64 t; cvta.to.shared.u64 t, %1; cvt.u32.u64 %0, t; }" : "=r"(a) : "l"(p));
    return a;
}
__device__ __forceinline__ void ldsm_x4(uint32_t addr, uint32_t* r) {
    asm volatile("ldmatrix.sync.aligned.m8n8.x4.shared.b16 {%0,%1,%2,%3}, [%4];"
        : "=r"(r[0]), "=r"(r[1]), "=r"(r[2]), "=r"(r[3]) : "r"(addr));
}
__device__ __forceinline__ void mma16816(float* c, const uint32_t* a, const uint32_t* b) {
    asm volatile(
        "mma.sync.aligned.m16n8k16.row.col.f32.bf16.bf16.f32 "
        "{%0,%1,%2,%3}, {%4,%5,%6,%7}, {%8,%9}, {%0,%1,%2,%3};"
        : "+f"(c[0]), "+f"(c[1]), "+f"(c[2]), "+f"(c[3])
        : "r"(a[0]), "r"(a[1]), "r"(a[2]), "r"(a[3]), "r"(b[0]), "r"(b[1]));
}
__device__ __forceinline__ void split_bf16(float v, __nv_bfloat16& h, __nv_bfloat16& l) {
    h = __float2bfloat16(v);
    l = __float2bfloat16(v - __bfloat162float(h));
}
// split a float4 into packed hi (uint2) and lo (uint2)
__device__ __forceinline__ void split_f4(float4 v, uint2& hi, uint2& lo) {
    __nv_bfloat16 h0, h1, h2, h3, l0, l1, l2, l3;
    split_bf16(v.x, h0, l0); split_bf16(v.y, h1, l1);
    split_bf16(v.z, h2, l2); split_bf16(v.w, h3, l3);
    __nv_bfloat162 ha = __halves2bfloat162(h0, h1), hb = __halves2bfloat162(h2, h3);
    __nv_bfloat162 la = __halves2bfloat162(l0, l1), lb = __halves2bfloat162(l2, l3);
    hi = make_uint2(*(uint32_t*)&ha, *(uint32_t*)&hb);
    lo = make_uint2(*(uint32_t*)&la, *(uint32_t*)&lb);
}

// ---------------- preprocessing kernels ------------------------------------
__global__ void k_init_deg(int n) {
    int i = blockIdx.x * blockDim.x + threadIdx.x;
    if (i < n) g_deg[i] = 1;
}
__global__ void k_hist(const int* __restrict__ ei, int e_cnt, int n) {
    int e = blockIdx.x * blockDim.x + threadIdx.x;
    if (e < e_cnt) {
        int d = ei[e_cnt + e];
        if ((unsigned)d < (unsigned)n) atomicAdd(&g_deg[d], 1);
    }
}
__global__ void k_finalize_deg(int n) {
    int i = blockIdx.x * blockDim.x + threadIdx.x;
    if (i < n) {
        int dg = g_deg[i];
        g_dinv[i] = rsqrtf((float)dg);
        g_cnt[i] = dg - 1;
    }
}
__global__ void k_scan(int n) {
    __shared__ int wsum[32];
    __shared__ int carry;
    int tid = threadIdx.x, lane = tid & 31, warp = tid >> 5;
    if (tid == 0) carry = 0;
    __syncthreads();
    for (int base = 0; base < n; base += 1024) {
        int i = base + tid;
        int v = (i < n) ? g_cnt[i] : 0;
        int x = v;
        #pragma unroll
        for (int s = 1; s < 32; s <<= 1) {
            int y = __shfl_up_sync(0xffffffffu, x, s);
            if (lane >= s) x += y;
        }
        if (lane == 31) wsum[warp] = x;
        __syncthreads();
        if (warp == 0) {
            int w = wsum[lane];
            #pragma unroll
            for (int s = 1; s < 32; s <<= 1) {
                int y = __shfl_up_sync(0xffffffffu, w, s);
                if (lane >= s) w += y;
            }
            wsum[lane] = w;
        }
        __syncthreads();
        int woff = (warp > 0) ? wsum[warp - 1] : 0;
        if (i < n) { g_off[i] = carry + woff + x - v; g_cur[i] = g_off[i]; }
        int total = wsum[31];
        __syncthreads();
        if (tid == 0) carry += total;
        __syncthreads();
    }
}
__global__ void k_fill(const int* __restrict__ ei, int e_cnt, int n) {
    int e = blockIdx.x * blockDim.x + threadIdx.x;
    if (e < e_cnt) {
        int s = ei[e];
        int d = ei[e_cnt + e];
        if ((unsigned)d < (unsigned)n && (unsigned)s < (unsigned)n) {
            int pos = atomicAdd(&g_cur[d], 1);
            if ((unsigned)pos < (unsigned)N_EDGES) g_csr[pos] = s;
        }
    }
}
// W1 [512,256] -> W1^T hi/lo [256,512]
__global__ void k_prep_w1t(const float* __restrict__ W1) {
    int i = blockIdx.x * blockDim.x + threadIdx.x;
    if (i >= 256 * 512) return;
    int n = i >> 9, k = i & 511;
    __nv_bfloat16 h, l;
    split_bf16(W1[k * 256 + n], h, l);
    g_w1t_hi[i] = h; g_w1t_lo[i] = l;
}
// [Wmu|Wls] -> Wc^T hi/lo [256,256], plus fused bias
__global__ void k_prep_wct(const float* __restrict__ Wmu, const float* __restrict__ Wls,
                           const float* __restrict__ bmu, const float* __restrict__ bls) {
    int i = blockIdx.x * blockDim.x + threadIdx.x;
    if (i >= 256 * 256) return;
    int n = i >> 8, k = i & 255;
    float v = (n < 128) ? Wmu[k * 128 + n] : Wls[k * 128 + (n - 128)];
    __nv_bfloat16 h, l;
    split_bf16(v, h, l);
    g_wct_hi[i] = h; g_wct_lo[i] = l;
    if (i < 256) g_bc[i] = (i < 128) ? bmu[i] : bls[i - 128];
}

// ---------------- mma.sync GEMM: C[M,256] = A[M,K] @ B^T, split-bf16 --------
// CTA tile 128m x 64n x 32k; 8 warps of 32m x 32n; 3 products Ah*Bh+Ah*Bl+Al*Bh.
// Grid is (4 n-tiles, mt m-tiles): consecutive bids share the m-tile -> A L2 reuse.
// PHASE 1: A = x fp32 (K=512), split to hi/lo on the fly, B=W1^T -> g_buf1 fp32
// PHASE 2: A = g hi/lo pre-split (K=256), B=Wc^T -> out [2,M,128] + bias
template<int KTOT, int PHASE>
__global__ void __launch_bounds__(256, 2) k_gemm_mma(const float* __restrict__ Axf,
                                                     float* __restrict__ outp, int M) {
    constexpr int KT = KTOT / 32;
    const __nv_bfloat16* __restrict__ Bh = (PHASE == 1) ? g_w1t_hi : g_wct_hi;
    const __nv_bfloat16* __restrict__ Bl = (PHASE == 1) ? g_w1t_lo : g_wct_lo;

    __shared__ uint16_t sAh[128 * 40], sAl[128 * 40];
    __shared__ uint16_t sBh[64 * 40],  sBl[64 * 40];

    int tid = threadIdx.x;
    int wid = tid >> 5, lane = tid & 31;
    int n0 = blockIdx.x * 64;
    int m0 = blockIdx.y * 128;

    // warp layout: 4 (m) x 2 (n); warp tile 32m x 32n
    int wm = (wid & 3) * 32;
    int wn = (wid >> 2) * 32;

    uint32_t sAh_b = smem_u32(sAh), sAl_b = smem_u32(sAl);
    uint32_t sBh_b = smem_u32(sBh), sBl_b = smem_u32(sBl);

    // ldmatrix lane addressing offsets
    int sub = lane >> 3, lr = lane & 7;
    uint32_t a_off = (uint32_t)((wm + lr + (sub & 1) * 8) * 80 + ((sub >> 1) * 8) * 2);
    uint32_t b_off = (uint32_t)((wn + lr + (sub >> 1) * 8) * 80 + ((sub & 1) * 8) * 2);

    float c[2][4][4];
    #pragma unroll
    for (int i = 0; i < 2; i++)
        #pragma unroll
        for (int j = 0; j < 4; j++)
            #pragma unroll
            for (int q = 0; q < 4; q++) c[i][j][q] = 0.f;

    const uint4* B4h = (const uint4*)Bh;
    const uint4* B4l = (const uint4*)Bl;
    int brow = tid >> 2, bchk = tid & 3;

    // -------- A-loader state --------
    // PHASE 1: 128 rows x 32 fp32; 1024 float4; 4 per thread (row=idx>>3, quad=idx&7)
    // PHASE 2: 128 rows x 32 bf16 hi+lo; 512 uint4 each; 2 per thread (row=idx>>2, chk=idx&3)
    float4 pX[4];
    uint4  pAh2[2], pAl2[2];
    uint4  pBhv, pBlv;

    auto ldg_tile = [&](int kt) {
        int ktk = kt * 32;
        if (PHASE == 1) {
            #pragma unroll
            for (int it = 0; it < 4; it++) {
                int idx = it * 256 + tid;
                int row = idx >> 3, quad = idx & 7;
                int gm = m0 + row; if (gm >= M) gm = M - 1;
                pX[it] = ((const float4*)Axf)[((long)gm * KTOT + ktk) / 4 + quad];
            }
        } else {
            #pragma unroll
            for (int it = 0; it < 2; it++) {
                int idx = it * 256 + tid;
                int row = idx >> 2, chk = idx & 3;
                int gm = m0 + row; if (gm >= M) gm = M - 1;
                long gi = ((long)gm * KTOT + ktk) >> 3;
                pAh2[it] = ((const uint4*)g_g_hi)[gi + chk];
                pAl2[it] = ((const uint4*)g_g_lo)[gi + chk];
            }
        }
        long gb = ((long)(n0 + brow) * KTOT + ktk) >> 3;
        pBhv = B4h[gb + bchk];
        pBlv = B4l[gb + bchk];
    };
    auto sts_tile = [&]() {
        if (PHASE == 1) {
            #pragma unroll
            for (int it = 0; it < 4; it++) {
                int idx = it * 256 + tid;
                int row = idx >> 3, quad = idx & 7;
                uint2 hi, lo;
                split_f4(pX[it], hi, lo);
                uint32_t so = (uint32_t)(row * 80 + quad * 8);
                *(uint2*)((char*)sAh + so) = hi;
                *(uint2*)((char*)sAl + so) = lo;
            }
        } else {
            #pragma unroll
            for (int it = 0; it < 2; it++) {
                int idx = it * 256 + tid;
                int row = idx >> 2, chk = idx & 3;
                uint32_t so = (uint32_t)(row * 80 + chk * 16);
                *(uint4*)((char*)sAh + so) = pAh2[it];
                *(uint4*)((char*)sAl + so) = pAl2[it];
            }
        }
        uint32_t sb = (uint32_t)(brow * 80 + bchk * 16);
        *(uint4*)((char*)sBh + sb) = pBhv;
        *(uint4*)((char*)sBl + sb) = pBlv;
    };

    ldg_tile(0);
    for (int kt = 0; kt < KT; kt++) {
        __syncthreads();
        sts_tile();
        __syncthreads();
        if (kt + 1 < KT) ldg_tile(kt + 1);   // overlap LDG with mma

        #pragma unroll
        for (int ks = 0; ks < 2; ks++) {
            uint32_t koff = (uint32_t)(ks * 16 * 2);
            uint32_t ah[2][4], al[2][4], bh[2][4], bl[2][4];
            #pragma unroll
            for (int mi = 0; mi < 2; mi++) {
                ldsm_x4(sAh_b + a_off + mi * 16 * 80 + koff, ah[mi]);
                ldsm_x4(sAl_b + a_off + mi * 16 * 80 + koff, al[mi]);
            }
            #pragma unroll
            for (int nb = 0; nb < 2; nb++) {
                ldsm_x4(sBh_b + b_off + nb * 16 * 80 + koff, bh[nb]);
                ldsm_x4(sBl_b + b_off + nb * 16 * 80 + koff, bl[nb]);
            }
            #pragma unroll
            for (int mi = 0; mi < 2; mi++)
                #pragma unroll
                for (int nj = 0; nj < 4; nj++) {
                    uint32_t bfh[2] = { bh[nj >> 1][(nj & 1) * 2], bh[nj >> 1][(nj & 1) * 2 + 1] };
                    uint32_t bfl[2] = { bl[nj >> 1][(nj & 1) * 2], bl[nj >> 1][(nj & 1) * 2 + 1] };
                    mma16816(c[mi][nj], ah[mi], bfh);
                    mma16816(c[mi][nj], ah[mi], bfl);
                    mma16816(c[mi][nj], al[mi], bfh);
                }
        }
    }

    // epilogue
    int mrow = (lane >> 2);
    int ncol = (lane & 3) * 2;
    #pragma unroll
    for (int mi = 0; mi < 2; mi++) {
        #pragma unroll
        for (int nj = 0; nj < 4; nj++) {
            int n_g = n0 + wn + nj * 8 + ncol;
            #pragma unroll
            for (int h = 0; h < 2; h++) {
                int m_g = m0 + wm + mi * 16 + mrow + h * 8;
                if (m_g < M) {
                    float v0 = c[mi][nj][h * 2], v1 = c[mi][nj][h * 2 + 1];
                    if (PHASE == 1) {
                        *(float2*)&g_buf1[(size_t)m_g * 256 + n_g] = make_float2(v0, v1);
                    } else {
                        int half = n_g >> 7, cc = n_g & 127;
                        float2 o = make_float2(v0 + g_bc[n_g], v1 + g_bc[n_g + 1]);
                        *(float2*)&outp[((size_t)half * M + m_g) * 128 + cc] = o;
                    }
                }
            }
        }
    }
}

// ---------------- aggregation: gather-style, one CTA (64 thr) per node -----
// out[d] = dinv[d] * ( dinv[d]*in[d] + sum_{s in csr(d)} dinv[s]*in[s] )
// PASS 1: g_buf1 -> g_buf2, relu(. + b1)
// PASS 2: g_buf2 -> g_g_hi/g_g_lo (split bf16)
// Edge loop unrolled x4 for MLP on the L2-latency-bound gather chain.
template<int PASS>
__global__ void k_agg(const float* __restrict__ bias, int M) {
    int d = blockIdx.x;
    if (d >= M) return;
    const float4* __restrict__ F = (const float4*)(PASS == 1 ? g_buf1 : g_buf2);
    int c = threadIdx.x;  // 0..63
    float wd = g_dinv[d];
    float4 v = F[(size_t)d * 64 + c];
    float4 acc = make_float4(wd * v.x, wd * v.y, wd * v.z, wd * v.w);
    int b = g_off[d];
    int n = g_cnt[d];
    int i = 0;
    for (; i + 4 <= n; i += 4) {
        int s0 = g_csr[b + i], s1 = g_csr[b + i + 1];
        int s2 = g_csr[b + i + 2], s3 = g_csr[b + i + 3];
        float w0 = g_dinv[s0], w1 = g_dinv[s1], w2 = g_dinv[s2], w3 = g_dinv[s3];
        float4 u0 = F[(size_t)s0 * 64 + c];
        float4 u1 = F[(size_t)s1 * 64 + c];
        float4 u2 = F[(size_t)s2 * 64 + c];
        float4 u3 = F[(size_t)s3 * 64 + c];
        acc.x += w0 * u0.x + w1 * u1.x + w2 * u2.x + w3 * u3.x;
        acc.y += w0 * u0.y + w1 * u1.y + w2 * u2.y + w3 * u3.y;
        acc.z += w0 * u0.z + w1 * u1.z + w2 * u2.z + w3 * u3.z;
        acc.w += w0 * u0.w + w1 * u1.w + w2 * u2.w + w3 * u3.w;
    }
    for (; i < n; i++) {
        int s = g_csr[b + i];
        float w = g_dinv[s];
        float4 u = F[(size_t)s * 64 + c];
        acc.x += w * u.x; acc.y += w * u.y; acc.z += w * u.z; acc.w += w * u.w;
    }
    acc.x *= wd; acc.y *= wd; acc.z *= wd; acc.w *= wd;
    if (PASS == 1) {
        float4 bb = ((const float4*)bias)[c];
        acc.x = fmaxf(acc.x + bb.x, 0.f);
        acc.y = fmaxf(acc.y + bb.y, 0.f);
        acc.z = fmaxf(acc.z + bb.z, 0.f);
        acc.w = fmaxf(acc.w + bb.w, 0.f);
        *(float4*)&g_buf2[(size_t)d * 256 + c * 4] = acc;
    } else {
        uint2 hi, lo;
        split_f4(acc, hi, lo);
        ((uint2*)g_g_hi)[(size_t)d * 64 + c] = hi;
        ((uint2*)g_g_lo)[(size_t)d * 64 + c] = lo;
    }
}

// ---------------- launch ----------------------------------------------------
extern "C" void kernel_launch(void* const* d_in, const int* in_sizes, int n_in,
                              void* d_out, int out_size) {
    const float* x   = (const float*)d_in[0];
    const int*   ei  = (const int*)d_in[1];
    const float* W1  = (const float*)d_in[2];
    const float* b1  = (const float*)d_in[3];
    const float* Wmu = (const float*)d_in[4];
    const float* bmu = (const float*)d_in[5];
    const float* Wls = (const float*)d_in[6];
    const float* bls = (const float*)d_in[7];
    float* out = (float*)d_out;

    int N = in_sizes[0] / 512;   // 50000
    int E = in_sizes[1] / 2;     // 800000

    // preprocessing (CSR + degrees) and weight conversion
    k_init_deg<<<(N + 255) / 256, 256>>>(N);
    k_prep_w1t<<<(256 * 512 + 255) / 256, 256>>>(W1);
    k_prep_wct<<<(256 * 256 + 255) / 256, 256>>>(Wmu, Wls, bmu, bls);
    k_hist<<<(E + 255) / 256, 256>>>(ei, E, N);
    k_finalize_deg<<<(N + 255) / 256, 256>>>(N);
    k_scan<<<1, 1024>>>(N);
    k_fill<<<(E + 255) / 256, 256>>>(ei, E, N);

    int mt = (N + 127) / 128;
    // layer 1: xw = x @ W1 (tensor cores, inline fp32->bf16 split);
    //          h = relu(dinv*Agg(dinv*xw) + b1)
    k_gemm_mma<512, 1><<<dim3(4, mt), 256>>>(x, nullptr, N);
    k_agg<1><<<N, 64>>>(b1, N);
    // layer 2: g = dinv*Agg(dinv*h) (split-bf16 out); [mu|ls] = g @ Wc + bc
    k_agg<2><<<N, 64>>>(nullptr, N);
    k_gemm_mma<256, 2><<<dim3(4, mt), 256>>>(nullptr, out, N);
}

// round 6
// speedup vs baseline: 2.9749x; 1.0494x over previous
#include <cuda_runtime.h>
#include <cuda_bf16.h>
#include <cstdint>

#define N_NODES 50000
#define N_EDGES 800000

// ---------------- scratch (device globals; no allocation allowed) ----------
__device__ float g_buf1[(size_t)N_NODES * 256];   // xw (GEMM1 out), agg1 input
__device__ float g_buf2[(size_t)N_NODES * 256];   // h (post-relu), agg2 input
__device__ __nv_bfloat16 g_g_hi[(size_t)N_NODES * 256];  // agg2 output split
__device__ __nv_bfloat16 g_g_lo[(size_t)N_NODES * 256];
__device__ __nv_bfloat16 g_w1t_hi[256 * 512];     // W1^T  [n,k]
__device__ __nv_bfloat16 g_w1t_lo[256 * 512];
__device__ __nv_bfloat16 g_wct_hi[256 * 256];     // [Wmu|Wls]^T  [n,k]
__device__ __nv_bfloat16 g_wct_lo[256 * 256];
__device__ float g_bc[256];                       // [b_mu | b_ls]
__device__ int   g_deg[N_NODES];                  // real in-degree (no self loop)
__device__ float g_dinv[N_NODES];
__device__ int   g_cnt[N_NODES];
__device__ int   g_off[N_NODES];
__device__ int   g_cur[N_NODES];
__device__ int   g_csr[N_EDGES];

// ---------------- helpers ----------------------------------------------------
__device__ __forceinline__ uint32_t smem_u32(const void* p) {
    uint32_t a;
    asm("{ .reg .u64 t; cvta.to.shared.u64 t, %1; cvt.u32.u64 %0, t; }" : "=r"(a) : "l"(p));
    return a;
}
__device__ __forceinline__ void ldsm_x4(uint32_t addr, uint32_t* r) {
    asm volatile("ldmatrix.sync.aligned.m8n8.x4.shared.b16 {%0,%1,%2,%3}, [%4];"
        : "=r"(r[0]), "=r"(r[1]), "=r"(r[2]), "=r"(r[3]) : "r"(addr));
}
__device__ __forceinline__ void mma16816(float* c, const uint32_t* a, const uint32_t* b) {
    asm volatile(
        "mma.sync.aligned.m16n8k16.row.col.f32.bf16.bf16.f32 "
        "{%0,%1,%2,%3}, {%4,%5,%6,%7}, {%8,%9}, {%0,%1,%2,%3};"
        : "+f"(c[0]), "+f"(c[1]), "+f"(c[2]), "+f"(c[3])
        : "r"(a[0]), "r"(a[1]), "r"(a[2]), "r"(a[3]), "r"(b[0]), "r"(b[1]));
}
__device__ __forceinline__ void split_bf16(float v, __nv_bfloat16& h, __nv_bfloat16& l) {
    h = __float2bfloat16(v);
    l = __float2bfloat16(v - __bfloat162float(h));
}
__device__ __forceinline__ void split_f4(float4 v, uint2& hi, uint2& lo) {
    __nv_bfloat16 h0, h1, h2, h3, l0, l1, l2, l3;
    split_bf16(v.x, h0, l0); split_bf16(v.y, h1, l1);
    split_bf16(v.z, h2, l2); split_bf16(v.w, h3, l3);
    __nv_bfloat162 ha = __halves2bfloat162(h0, h1), hb = __halves2bfloat162(h2, h3);
    __nv_bfloat162 la = __halves2bfloat162(l0, l1), lb = __halves2bfloat162(l2, l3);
    hi = make_uint2(*(uint32_t*)&ha, *(uint32_t*)&hb);
    lo = make_uint2(*(uint32_t*)&la, *(uint32_t*)&lb);
}

// ---------------- preprocessing kernels ------------------------------------
__global__ void k_init_deg(int n) {
    int i = blockIdx.x * blockDim.x + threadIdx.x;
    if (i < n) g_deg[i] = 0;
}
__global__ void k_hist(const int* __restrict__ ei, int e_cnt, int n) {
    int e = blockIdx.x * blockDim.x + threadIdx.x;
    if (e < e_cnt) {
        int d = ei[e_cnt + e];
        if ((unsigned)d < (unsigned)n) atomicAdd(&g_deg[d], 1);
    }
}
// fused: dinv/cnt from deg + single-block exclusive scan -> off/cur
__global__ void k_scanfin(int n) {
    __shared__ int wsum[32];
    __shared__ int carry;
    int tid = threadIdx.x, lane = tid & 31, warp = tid >> 5;
    if (tid == 0) carry = 0;
    __syncthreads();
    for (int base = 0; base < n; base += 1024) {
        int i = base + tid;
        int v = 0;
        if (i < n) {
            int dg = g_deg[i];                 // real in-edges
            g_dinv[i] = rsqrtf((float)(dg + 1));  // +1 self loop
            g_cnt[i] = dg;
            v = dg;
        }
        int x = v;
        #pragma unroll
        for (int s = 1; s < 32; s <<= 1) {
            int y = __shfl_up_sync(0xffffffffu, x, s);
            if (lane >= s) x += y;
        }
        if (lane == 31) wsum[warp] = x;
        __syncthreads();
        if (warp == 0) {
            int w = wsum[lane];
            #pragma unroll
            for (int s = 1; s < 32; s <<= 1) {
                int y = __shfl_up_sync(0xffffffffu, w, s);
                if (lane >= s) w += y;
            }
            wsum[lane] = w;
        }
        __syncthreads();
        int woff = (warp > 0) ? wsum[warp - 1] : 0;
        if (i < n) {
            int excl = carry + woff + x - v;
            g_off[i] = excl; g_cur[i] = excl;
        }
        int total = wsum[31];
        __syncthreads();
        if (tid == 0) carry += total;
        __syncthreads();
    }
}
__global__ void k_fill(const int* __restrict__ ei, int e_cnt, int n) {
    int e = blockIdx.x * blockDim.x + threadIdx.x;
    if (e < e_cnt) {
        int s = ei[e];
        int d = ei[e_cnt + e];
        if ((unsigned)d < (unsigned)n && (unsigned)s < (unsigned)n) {
            int pos = atomicAdd(&g_cur[d], 1);
            if ((unsigned)pos < (unsigned)N_EDGES) g_csr[pos] = s;
        }
    }
}
// W1 [512,256] -> W1^T hi/lo [256,512]
__global__ void k_prep_w1t(const float* __restrict__ W1) {
    int i = blockIdx.x * blockDim.x + threadIdx.x;
    if (i >= 256 * 512) return;
    int n = i >> 9, k = i & 511;
    __nv_bfloat16 h, l;
    split_bf16(W1[k * 256 + n], h, l);
    g_w1t_hi[i] = h; g_w1t_lo[i] = l;
}
// [Wmu|Wls] -> Wc^T hi/lo [256,256], plus fused bias
__global__ void k_prep_wct(const float* __restrict__ Wmu, const float* __restrict__ Wls,
                           const float* __restrict__ bmu, const float* __restrict__ bls) {
    int i = blockIdx.x * blockDim.x + threadIdx.x;
    if (i >= 256 * 256) return;
    int n = i >> 8, k = i & 255;
    float v = (n < 128) ? Wmu[k * 128 + n] : Wls[k * 128 + (n - 128)];
    __nv_bfloat16 h, l;
    split_bf16(v, h, l);
    g_wct_hi[i] = h; g_wct_lo[i] = l;
    if (i < 256) g_bc[i] = (i < 128) ? bmu[i] : bls[i - 128];
}

// ---------------- mma.sync GEMM: C[M,256] = A[M,K] @ B^T, split-bf16 --------
// CTA tile 128m x 64n x 32k; 8 warps of 32m x 32n; 3 products Ah*Bh+Ah*Bl+Al*Bh.
// Grid is (4 n-tiles, mt m-tiles): consecutive bids share the m-tile -> A L2 reuse.
template<int KTOT, int PHASE>
__global__ void __launch_bounds__(256, 2) k_gemm_mma(const float* __restrict__ Axf,
                                                     float* __restrict__ outp, int M) {
    constexpr int KT = KTOT / 32;
    const __nv_bfloat16* __restrict__ Bh = (PHASE == 1) ? g_w1t_hi : g_wct_hi;
    const __nv_bfloat16* __restrict__ Bl = (PHASE == 1) ? g_w1t_lo : g_wct_lo;

    __shared__ uint16_t sAh[128 * 40], sAl[128 * 40];
    __shared__ uint16_t sBh[64 * 40],  sBl[64 * 40];

    int tid = threadIdx.x;
    int wid = tid >> 5, lane = tid & 31;
    int n0 = blockIdx.x * 64;
    int m0 = blockIdx.y * 128;

    int wm = (wid & 3) * 32;
    int wn = (wid >> 2) * 32;

    uint32_t sAh_b = smem_u32(sAh), sAl_b = smem_u32(sAl);
    uint32_t sBh_b = smem_u32(sBh), sBl_b = smem_u32(sBl);

    int sub = lane >> 3, lr = lane & 7;
    uint32_t a_off = (uint32_t)((wm + lr + (sub & 1) * 8) * 80 + ((sub >> 1) * 8) * 2);
    uint32_t b_off = (uint32_t)((wn + lr + (sub >> 1) * 8) * 80 + ((sub & 1) * 8) * 2);

    float c[2][4][4];
    #pragma unroll
    for (int i = 0; i < 2; i++)
        #pragma unroll
        for (int j = 0; j < 4; j++)
            #pragma unroll
            for (int q = 0; q < 4; q++) c[i][j][q] = 0.f;

    const uint4* B4h = (const uint4*)Bh;
    const uint4* B4l = (const uint4*)Bl;
    int brow = tid >> 2, bchk = tid & 3;

    float4 pX[4];
    uint4  pAh2[2], pAl2[2];
    uint4  pBhv, pBlv;

    auto ldg_tile = [&](int kt) {
        int ktk = kt * 32;
        if (PHASE == 1) {
            #pragma unroll
            for (int it = 0; it < 4; it++) {
                int idx = it * 256 + tid;
                int row = idx >> 3, quad = idx & 7;
                int gm = m0 + row; if (gm >= M) gm = M - 1;
                pX[it] = ((const float4*)Axf)[((long)gm * KTOT + ktk) / 4 + quad];
            }
        } else {
            #pragma unroll
            for (int it = 0; it < 2; it++) {
                int idx = it * 256 + tid;
                int row = idx >> 2, chk = idx & 3;
                int gm = m0 + row; if (gm >= M) gm = M - 1;
                long gi = ((long)gm * KTOT + ktk) >> 3;
                pAh2[it] = ((const uint4*)g_g_hi)[gi + chk];
                pAl2[it] = ((const uint4*)g_g_lo)[gi + chk];
            }
        }
        long gb = ((long)(n0 + brow) * KTOT + ktk) >> 3;
        pBhv = B4h[gb + bchk];
        pBlv = B4l[gb + bchk];
    };
    auto sts_tile = [&]() {
        if (PHASE == 1) {
            #pragma unroll
            for (int it = 0; it < 4; it++) {
                int idx = it * 256 + tid;
                int row = idx >> 3, quad = idx & 7;
                uint2 hi, lo;
                split_f4(pX[it], hi, lo);
                uint32_t so = (uint32_t)(row * 80 + quad * 8);
                *(uint2*)((char*)sAh + so) = hi;
                *(uint2*)((char*)sAl + so) = lo;
            }
        } else {
            #pragma unroll
            for (int it = 0; it < 2; it++) {
                int idx = it * 256 + tid;
                int row = idx >> 2, chk = idx & 3;
                uint32_t so = (uint32_t)(row * 80 + chk * 16);
                *(uint4*)((char*)sAh + so) = pAh2[it];
                *(uint4*)((char*)sAl + so) = pAl2[it];
            }
        }
        uint32_t sb = (uint32_t)(brow * 80 + bchk * 16);
        *(uint4*)((char*)sBh + sb) = pBhv;
        *(uint4*)((char*)sBl + sb) = pBlv;
    };

    ldg_tile(0);
    for (int kt = 0; kt < KT; kt++) {
        __syncthreads();
        sts_tile();
        __syncthreads();
        if (kt + 1 < KT) ldg_tile(kt + 1);

        #pragma unroll
        for (int ks = 0; ks < 2; ks++) {
            uint32_t koff = (uint32_t)(ks * 16 * 2);
            uint32_t ah[2][4], al[2][4], bh[2][4], bl[2][4];
            #pragma unroll
            for (int mi = 0; mi < 2; mi++) {
                ldsm_x4(sAh_b + a_off + mi * 16 * 80 + koff, ah[mi]);
                ldsm_x4(sAl_b + a_off + mi * 16 * 80 + koff, al[mi]);
            }
            #pragma unroll
            for (int nb = 0; nb < 2; nb++) {
                ldsm_x4(sBh_b + b_off + nb * 16 * 80 + koff, bh[nb]);
                ldsm_x4(sBl_b + b_off + nb * 16 * 80 + koff, bl[nb]);
            }
            #pragma unroll
            for (int mi = 0; mi < 2; mi++)
                #pragma unroll
                for (int nj = 0; nj < 4; nj++) {
                    uint32_t bfh[2] = { bh[nj >> 1][(nj & 1) * 2], bh[nj >> 1][(nj & 1) * 2 + 1] };
                    uint32_t bfl[2] = { bl[nj >> 1][(nj & 1) * 2], bl[nj >> 1][(nj & 1) * 2 + 1] };
                    mma16816(c[mi][nj], ah[mi], bfh);
                    mma16816(c[mi][nj], ah[mi], bfl);
                    mma16816(c[mi][nj], al[mi], bfh);
                }
        }
    }

    int mrow = (lane >> 2);
    int ncol = (lane & 3) * 2;
    #pragma unroll
    for (int mi = 0; mi < 2; mi++) {
        #pragma unroll
        for (int nj = 0; nj < 4; nj++) {
            int n_g = n0 + wn + nj * 8 + ncol;
            #pragma unroll
            for (int h = 0; h < 2; h++) {
                int m_g = m0 + wm + mi * 16 + mrow + h * 8;
                if (m_g < M) {
                    float v0 = c[mi][nj][h * 2], v1 = c[mi][nj][h * 2 + 1];
                    if (PHASE == 1) {
                        *(float2*)&g_buf1[(size_t)m_g * 256 + n_g] = make_float2(v0, v1);
                    } else {
                        int half = n_g >> 7, cc = n_g & 127;
                        float2 o = make_float2(v0 + g_bc[n_g], v1 + g_bc[n_g + 1]);
                        *(float2*)&outp[((size_t)half * M + m_g) * 128 + cc] = o;
                    }
                }
            }
        }
    }
}

// ---------------- aggregation: gather-style, one CTA (64 thr) per node -----
// out[d] = dinv[d] * ( dinv[d]*in[d] + sum_{s in csr(d)} dinv[s]*in[s] )
// Edge loop unrolled x8 for MLP on the L2-latency-bound gather chain.
template<int PASS>
__global__ void k_agg(const float* __restrict__ bias, int M) {
    int d = blockIdx.x;
    if (d >= M) return;
    const float4* __restrict__ F = (const float4*)(PASS == 1 ? g_buf1 : g_buf2);
    int c = threadIdx.x;  // 0..63
    float wd = g_dinv[d];
    float4 v = F[(size_t)d * 64 + c];
    float4 acc = make_float4(wd * v.x, wd * v.y, wd * v.z, wd * v.w);
    int b = g_off[d];
    int n = g_cnt[d];
    int i = 0;
    for (; i + 8 <= n; i += 8) {
        int   s[8];
        float w[8];
        #pragma unroll
        for (int q = 0; q < 8; q++) s[q] = g_csr[b + i + q];
        #pragma unroll
        for (int q = 0; q < 8; q++) w[q] = g_dinv[s[q]];
        float4 u[8];
        #pragma unroll
        for (int q = 0; q < 8; q++) u[q] = F[(size_t)s[q] * 64 + c];
        #pragma unroll
        for (int q = 0; q < 8; q++) {
            acc.x += w[q] * u[q].x;
            acc.y += w[q] * u[q].y;
            acc.z += w[q] * u[q].z;
            acc.w += w[q] * u[q].w;
        }
    }
    for (; i < n; i++) {
        int s0 = g_csr[b + i];
        float w0 = g_dinv[s0];
        float4 u0 = F[(size_t)s0 * 64 + c];
        acc.x += w0 * u0.x; acc.y += w0 * u0.y; acc.z += w0 * u0.z; acc.w += w0 * u0.w;
    }
    acc.x *= wd; acc.y *= wd; acc.z *= wd; acc.w *= wd;
    if (PASS == 1) {
        float4 bb = ((const float4*)bias)[c];
        acc.x = fmaxf(acc.x + bb.x, 0.f);
        acc.y = fmaxf(acc.y + bb.y, 0.f);
        acc.z = fmaxf(acc.z + bb.z, 0.f);
        acc.w = fmaxf(acc.w + bb.w, 0.f);
        *(float4*)&g_buf2[(size_t)d * 256 + c * 4] = acc;
    } else {
        uint2 hi, lo;
        split_f4(acc, hi, lo);
        ((uint2*)g_g_hi)[(size_t)d * 64 + c] = hi;
        ((uint2*)g_g_lo)[(size_t)d * 64 + c] = lo;
    }
}

// ---------------- launch ----------------------------------------------------
extern "C" void kernel_launch(void* const* d_in, const int* in_sizes, int n_in,
                              void* d_out, int out_size) {
    const float* x   = (const float*)d_in[0];
    const int*   ei  = (const int*)d_in[1];
    const float* W1  = (const float*)d_in[2];
    const float* b1  = (const float*)d_in[3];
    const float* Wmu = (const float*)d_in[4];
    const float* bmu = (const float*)d_in[5];
    const float* Wls = (const float*)d_in[6];
    const float* bls = (const float*)d_in[7];
    float* out = (float*)d_out;

    int N = in_sizes[0] / 512;   // 50000
    int E = in_sizes[1] / 2;     // 800000
    int mt = (N + 127) / 128;

    // one-time resource init (no device memory involved)
    static cudaStream_t sB = nullptr;
    static cudaEvent_t evFork = nullptr, evJoin = nullptr, evW = nullptr;
    if (sB == nullptr) {
        cudaStreamCreateWithFlags(&sB, cudaStreamNonBlocking);
        cudaEventCreateWithFlags(&evFork, cudaEventDisableTiming);
        cudaEventCreateWithFlags(&evJoin, cudaEventDisableTiming);
        cudaEventCreateWithFlags(&evW, cudaEventDisableTiming);
    }

    // fork: side stream handles CSR build + layer-2 weight prep, overlapping GEMM1
    cudaEventRecord(evFork, 0);
    cudaStreamWaitEvent(sB, evFork, 0);

    k_prep_w1t<<<(256 * 512 + 255) / 256, 256>>>(W1);                    // s0
    k_init_deg<<<(N + 255) / 256, 256, 0, sB>>>(N);                      // sB
    k_hist<<<(E + 255) / 256, 256, 0, sB>>>(ei, E, N);                   // sB
    // layer 1 GEMM (submitted 4th so the profiler window lands on it)
    k_gemm_mma<512, 1><<<dim3(4, mt), 256>>>(x, nullptr, N);             // s0
    k_scanfin<<<1, 1024, 0, sB>>>(N);                                    // sB
    k_fill<<<(E + 255) / 256, 256, 0, sB>>>(ei, E, N);                   // sB
    cudaEventRecord(evJoin, sB);
    k_prep_wct<<<(256 * 256 + 255) / 256, 256, 0, sB>>>(Wmu, Wls, bmu, bls);  // sB
    cudaEventRecord(evW, sB);

    // join: aggregation needs GEMM1 (s0 order) + CSR/dinv (evJoin)
    cudaStreamWaitEvent(0, evJoin, 0);
    k_agg<1><<<N, 64>>>(b1, N);
    k_agg<2><<<N, 64>>>(nullptr, N);
    cudaStreamWaitEvent(0, evW, 0);     // rejoin sB fully before last kernel
    k_gemm_mma<256, 2><<<dim3(4, mt), 256>>>(nullptr, out, N);
}

// round 7
// speedup vs baseline: 2.9780x; 1.0010x over previous
#include <cuda_runtime.h>
#include <cuda_bf16.h>
#include <cstdint>

#define N_NODES 50000
#define N_EDGES 800000

// ---------------- scratch (device globals; no allocation allowed) ----------
__device__ float g_buf1[(size_t)N_NODES * 256];   // xw (GEMM1 out), agg1 input
__device__ float g_buf2[(size_t)N_NODES * 256];   // h (post-relu), agg2 input
__device__ __nv_bfloat16 g_g_hi[(size_t)N_NODES * 256];  // agg2 output split
__device__ __nv_bfloat16 g_g_lo[(size_t)N_NODES * 256];
__device__ __nv_bfloat16 g_w1t_hi[256 * 512];     // W1^T  [n,k]
__device__ __nv_bfloat16 g_w1t_lo[256 * 512];
__device__ __nv_bfloat16 g_wct_hi[256 * 256];     // [Wmu|Wls]^T  [n,k]
__device__ __nv_bfloat16 g_wct_lo[256 * 256];
__device__ float g_bc[256];                       // [b_mu | b_ls]
__device__ int   g_deg[N_NODES];                  // real in-degree (no self loop)
__device__ float g_dinv[N_NODES];
__device__ int   g_cnt[N_NODES];
__device__ int   g_off[N_NODES];
__device__ int   g_cur[N_NODES];
__device__ int   g_csr[N_EDGES];

// ---------------- helpers ----------------------------------------------------
__device__ __forceinline__ uint32_t smem_u32(const void* p) {
    uint32_t a;
    asm("{ .reg .u64 t; cvta.to.shared.u64 t, %1; cvt.u32.u64 %0, t; }" : "=r"(a) : "l"(p));
    return a;
}
__device__ __forceinline__ void ldsm_x4(uint32_t addr, uint32_t* r) {
    asm volatile("ldmatrix.sync.aligned.m8n8.x4.shared.b16 {%0,%1,%2,%3}, [%4];"
        : "=r"(r[0]), "=r"(r[1]), "=r"(r[2]), "=r"(r[3]) : "r"(addr));
}
__device__ __forceinline__ void mma16816(float* c, const uint32_t* a, const uint32_t* b) {
    asm volatile(
        "mma.sync.aligned.m16n8k16.row.col.f32.bf16.bf16.f32 "
        "{%0,%1,%2,%3}, {%4,%5,%6,%7}, {%8,%9}, {%0,%1,%2,%3};"
        : "+f"(c[0]), "+f"(c[1]), "+f"(c[2]), "+f"(c[3])
        : "r"(a[0]), "r"(a[1]), "r"(a[2]), "r"(a[3]), "r"(b[0]), "r"(b[1]));
}
__device__ __forceinline__ void split_bf16(float v, __nv_bfloat16& h, __nv_bfloat16& l) {
    h = __float2bfloat16(v);
    l = __float2bfloat16(v - __bfloat162float(h));
}
__device__ __forceinline__ void split_f4(float4 v, uint2& hi, uint2& lo) {
    __nv_bfloat16 h0, h1, h2, h3, l0, l1, l2, l3;
    split_bf16(v.x, h0, l0); split_bf16(v.y, h1, l1);
    split_bf16(v.z, h2, l2); split_bf16(v.w, h3, l3);
    __nv_bfloat162 ha = __halves2bfloat162(h0, h1), hb = __halves2bfloat162(h2, h3);
    __nv_bfloat162 la = __halves2bfloat162(l0, l1), lb = __halves2bfloat162(l2, l3);
    hi = make_uint2(*(uint32_t*)&ha, *(uint32_t*)&hb);
    lo = make_uint2(*(uint32_t*)&la, *(uint32_t*)&lb);
}

// ---------------- preprocessing kernels ------------------------------------
__global__ void k_init_deg(int n) {
    int i = blockIdx.x * blockDim.x + threadIdx.x;
    if (i < n) g_deg[i] = 0;
}
__global__ void k_hist(const int* __restrict__ ei, int e_cnt, int n) {
    int e = blockIdx.x * blockDim.x + threadIdx.x;
    if (e < e_cnt) {
        int d = ei[e_cnt + e];
        if ((unsigned)d < (unsigned)n) atomicAdd(&g_deg[d], 1);
    }
}
// fused: dinv/cnt from deg + single-block exclusive scan -> off/cur
__global__ void k_scanfin(int n) {
    __shared__ int wsum[32];
    __shared__ int carry;
    int tid = threadIdx.x, lane = tid & 31, warp = tid >> 5;
    if (tid == 0) carry = 0;
    __syncthreads();
    for (int base = 0; base < n; base += 1024) {
        int i = base + tid;
        int v = 0;
        if (i < n) {
            int dg = g_deg[i];
            g_dinv[i] = rsqrtf((float)(dg + 1));
            g_cnt[i] = dg;
            v = dg;
        }
        int x = v;
        #pragma unroll
        for (int s = 1; s < 32; s <<= 1) {
            int y = __shfl_up_sync(0xffffffffu, x, s);
            if (lane >= s) x += y;
        }
        if (lane == 31) wsum[warp] = x;
        __syncthreads();
        if (warp == 0) {
            int w = wsum[lane];
            #pragma unroll
            for (int s = 1; s < 32; s <<= 1) {
                int y = __shfl_up_sync(0xffffffffu, w, s);
                if (lane >= s) w += y;
            }
            wsum[lane] = w;
        }
        __syncthreads();
        int woff = (warp > 0) ? wsum[warp - 1] : 0;
        if (i < n) {
            int excl = carry + woff + x - v;
            g_off[i] = excl; g_cur[i] = excl;
        }
        int total = wsum[31];
        __syncthreads();
        if (tid == 0) carry += total;
        __syncthreads();
    }
}
__global__ void k_fill(const int* __restrict__ ei, int e_cnt, int n) {
    int e = blockIdx.x * blockDim.x + threadIdx.x;
    if (e < e_cnt) {
        int s = ei[e];
        int d = ei[e_cnt + e];
        if ((unsigned)d < (unsigned)n && (unsigned)s < (unsigned)n) {
            int pos = atomicAdd(&g_cur[d], 1);
            if ((unsigned)pos < (unsigned)N_EDGES) g_csr[pos] = s;
        }
    }
}
// W1 [512,256] -> W1^T hi/lo [256,512]
__global__ void k_prep_w1t(const float* __restrict__ W1) {
    int i = blockIdx.x * blockDim.x + threadIdx.x;
    if (i >= 256 * 512) return;
    int n = i >> 9, k = i & 511;
    __nv_bfloat16 h, l;
    split_bf16(W1[k * 256 + n], h, l);
    g_w1t_hi[i] = h; g_w1t_lo[i] = l;
}
// [Wmu|Wls] -> Wc^T hi/lo [256,256], plus fused bias
__global__ void k_prep_wct(const float* __restrict__ Wmu, const float* __restrict__ Wls,
                           const float* __restrict__ bmu, const float* __restrict__ bls) {
    int i = blockIdx.x * blockDim.x + threadIdx.x;
    if (i >= 256 * 256) return;
    int n = i >> 8, k = i & 255;
    float v = (n < 128) ? Wmu[k * 128 + n] : Wls[k * 128 + (n - 128)];
    __nv_bfloat16 h, l;
    split_bf16(v, h, l);
    g_wct_hi[i] = h; g_wct_lo[i] = l;
    if (i < 256) g_bc[i] = (i < 128) ? bmu[i] : bls[i - 128];
}

// ---------------- mma.sync GEMM: C[M,256] = A[M,K] @ B^T, split-bf16 --------
// CTA tile 128m x 128n x 32k; 8 warps of 32m x 64n (4m x 2n layout).
// 3 products Ah*Bh + Ah*Bl + Al*Bh. LDS/MAC = 0.183 B (was 0.244).
// Grid is (2 n-tiles, mt m-tiles): consecutive bids share the m-tile -> A L2 reuse.
template<int KTOT, int PHASE>
__global__ void __launch_bounds__(256, 1) k_gemm_mma(const float* __restrict__ Axf,
                                                     float* __restrict__ outp, int M) {
    constexpr int KT = KTOT / 32;
    const __nv_bfloat16* __restrict__ Bh = (PHASE == 1) ? g_w1t_hi : g_wct_hi;
    const __nv_bfloat16* __restrict__ Bl = (PHASE == 1) ? g_w1t_lo : g_wct_lo;

    __shared__ uint16_t sAh[128 * 40], sAl[128 * 40];
    __shared__ uint16_t sBh[128 * 40], sBl[128 * 40];

    int tid = threadIdx.x;
    int wid = tid >> 5, lane = tid & 31;
    int n0 = blockIdx.x * 128;
    int m0 = blockIdx.y * 128;

    int wm = (wid & 3) * 32;       // 4 m-warps
    int wn = (wid >> 2) * 64;      // 2 n-warps, 64 n each

    uint32_t sAh_b = smem_u32(sAh), sAl_b = smem_u32(sAl);
    uint32_t sBh_b = smem_u32(sBh), sBl_b = smem_u32(sBl);

    int sub = lane >> 3, lr = lane & 7;
    uint32_t a_off = (uint32_t)((wm + lr + (sub & 1) * 8) * 80 + ((sub >> 1) * 8) * 2);
    uint32_t b_off = (uint32_t)((wn + lr + (sub >> 1) * 8) * 80 + ((sub & 1) * 8) * 2);

    float c[2][8][4];
    #pragma unroll
    for (int i = 0; i < 2; i++)
        #pragma unroll
        for (int j = 0; j < 8; j++)
            #pragma unroll
            for (int q = 0; q < 4; q++) c[i][j][q] = 0.f;

    const uint4* B4h = (const uint4*)Bh;
    const uint4* B4l = (const uint4*)Bl;

    // -------- prefetch registers --------
    // A phase1: 128 rows x 32 fp32 = 1024 float4, 4/thread (row=idx>>3, quad=idx&7)
    // A phase2: 128 rows x 32 bf16 hi+lo = 512 uint4 each, 2/thread (row=idx>>2, chk=idx&3)
    // B: 128 rows x 32 bf16 hi+lo = 512 uint4 each, 2/thread
    float4 pX[4];
    uint4  pAh2[2], pAl2[2];
    uint4  pBhv[2], pBlv[2];

    auto ldg_tile = [&](int kt) {
        int ktk = kt * 32;
        if (PHASE == 1) {
            #pragma unroll
            for (int it = 0; it < 4; it++) {
                int idx = it * 256 + tid;
                int row = idx >> 3, quad = idx & 7;
                int gm = m0 + row; if (gm >= M) gm = M - 1;
                pX[it] = ((const float4*)Axf)[((long)gm * KTOT + ktk) / 4 + quad];
            }
        } else {
            #pragma unroll
            for (int it = 0; it < 2; it++) {
                int idx = it * 256 + tid;
                int row = idx >> 2, chk = idx & 3;
                int gm = m0 + row; if (gm >= M) gm = M - 1;
                long gi = ((long)gm * KTOT + ktk) >> 3;
                pAh2[it] = ((const uint4*)g_g_hi)[gi + chk];
                pAl2[it] = ((const uint4*)g_g_lo)[gi + chk];
            }
        }
        #pragma unroll
        for (int it = 0; it < 2; it++) {
            int idx = it * 256 + tid;
            int row = idx >> 2, chk = idx & 3;
            long gb = ((long)(n0 + row) * KTOT + ktk) >> 3;
            pBhv[it] = B4h[gb + chk];
            pBlv[it] = B4l[gb + chk];
        }
    };
    auto sts_tile = [&]() {
        if (PHASE == 1) {
            #pragma unroll
            for (int it = 0; it < 4; it++) {
                int idx = it * 256 + tid;
                int row = idx >> 3, quad = idx & 7;
                uint2 hi, lo;
                split_f4(pX[it], hi, lo);
                uint32_t so = (uint32_t)(row * 80 + quad * 8);
                *(uint2*)((char*)sAh + so) = hi;
                *(uint2*)((char*)sAl + so) = lo;
            }
        } else {
            #pragma unroll
            for (int it = 0; it < 2; it++) {
                int idx = it * 256 + tid;
                int row = idx >> 2, chk = idx & 3;
                uint32_t so = (uint32_t)(row * 80 + chk * 16);
                *(uint4*)((char*)sAh + so) = pAh2[it];
                *(uint4*)((char*)sAl + so) = pAl2[it];
            }
        }
        #pragma unroll
        for (int it = 0; it < 2; it++) {
            int idx = it * 256 + tid;
            int row = idx >> 2, chk = idx & 3;
            uint32_t so = (uint32_t)(row * 80 + chk * 16);
            *(uint4*)((char*)sBh + so) = pBhv[it];
            *(uint4*)((char*)sBl + so) = pBlv[it];
        }
    };

    ldg_tile(0);
    for (int kt = 0; kt < KT; kt++) {
        __syncthreads();
        sts_tile();
        __syncthreads();
        if (kt + 1 < KT) ldg_tile(kt + 1);   // overlap LDG with mma

        #pragma unroll
        for (int ks = 0; ks < 2; ks++) {
            uint32_t koff = (uint32_t)(ks * 16 * 2);
            uint32_t ah[2][4], al[2][4];
            #pragma unroll
            for (int mi = 0; mi < 2; mi++) {
                ldsm_x4(sAh_b + a_off + mi * 16 * 80 + koff, ah[mi]);
                ldsm_x4(sAl_b + a_off + mi * 16 * 80 + koff, al[mi]);
            }
            #pragma unroll
            for (int nb = 0; nb < 4; nb++) {   // 4 B fragments of 16n, loaded on demand
                uint32_t bh[4], bl[4];
                ldsm_x4(sBh_b + b_off + nb * 16 * 80 + koff, bh);
                ldsm_x4(sBl_b + b_off + nb * 16 * 80 + koff, bl);
                #pragma unroll
                for (int mi = 0; mi < 2; mi++)
                    #pragma unroll
                    for (int jj = 0; jj < 2; jj++) {
                        int nj = nb * 2 + jj;
                        uint32_t bfh[2] = { bh[jj * 2], bh[jj * 2 + 1] };
                        uint32_t bfl[2] = { bl[jj * 2], bl[jj * 2 + 1] };
                        mma16816(c[mi][nj], ah[mi], bfh);
                        mma16816(c[mi][nj], ah[mi], bfl);
                        mma16816(c[mi][nj], al[mi], bfh);
                    }
            }
        }
    }

    int mrow = (lane >> 2);
    int ncol = (lane & 3) * 2;
    #pragma unroll
    for (int mi = 0; mi < 2; mi++) {
        #pragma unroll
        for (int nj = 0; nj < 8; nj++) {
            int n_g = n0 + wn + nj * 8 + ncol;
            #pragma unroll
            for (int h = 0; h < 2; h++) {
                int m_g = m0 + wm + mi * 16 + mrow + h * 8;
                if (m_g < M) {
                    float v0 = c[mi][nj][h * 2], v1 = c[mi][nj][h * 2 + 1];
                    if (PHASE == 1) {
                        *(float2*)&g_buf1[(size_t)m_g * 256 + n_g] = make_float2(v0, v1);
                    } else {
                        int half = n_g >> 7, cc = n_g & 127;
                        float2 o = make_float2(v0 + g_bc[n_g], v1 + g_bc[n_g + 1]);
                        *(float2*)&outp[((size_t)half * M + m_g) * 128 + cc] = o;
                    }
                }
            }
        }
    }
}

// ---------------- aggregation: gather-style, one CTA (64 thr) per node -----
// out[d] = dinv[d] * ( dinv[d]*in[d] + sum_{s in csr(d)} dinv[s]*in[s] )
template<int PASS>
__global__ void k_agg(const float* __restrict__ bias, int M) {
    int d = blockIdx.x;
    if (d >= M) return;
    const float4* __restrict__ F = (const float4*)(PASS == 1 ? g_buf1 : g_buf2);
    int c = threadIdx.x;  // 0..63
    float wd = g_dinv[d];
    float4 v = F[(size_t)d * 64 + c];
    float4 acc = make_float4(wd * v.x, wd * v.y, wd * v.z, wd * v.w);
    int b = g_off[d];
    int n = g_cnt[d];
    int i = 0;
    for (; i + 8 <= n; i += 8) {
        int   s[8];
        float w[8];
        #pragma unroll
        for (int q = 0; q < 8; q++) s[q] = g_csr[b + i + q];
        #pragma unroll
        for (int q = 0; q < 8; q++) w[q] = g_dinv[s[q]];
        float4 u[8];
        #pragma unroll
        for (int q = 0; q < 8; q++) u[q] = F[(size_t)s[q] * 64 + c];
        #pragma unroll
        for (int q = 0; q < 8; q++) {
            acc.x += w[q] * u[q].x;
            acc.y += w[q] * u[q].y;
            acc.z += w[q] * u[q].z;
            acc.w += w[q] * u[q].w;
        }
    }
    for (; i < n; i++) {
        int s0 = g_csr[b + i];
        float w0 = g_dinv[s0];
        float4 u0 = F[(size_t)s0 * 64 + c];
        acc.x += w0 * u0.x; acc.y += w0 * u0.y; acc.z += w0 * u0.z; acc.w += w0 * u0.w;
    }
    acc.x *= wd; acc.y *= wd; acc.z *= wd; acc.w *= wd;
    if (PASS == 1) {
        float4 bb = ((const float4*)bias)[c];
        acc.x = fmaxf(acc.x + bb.x, 0.f);
        acc.y = fmaxf(acc.y + bb.y, 0.f);
        acc.z = fmaxf(acc.z + bb.z, 0.f);
        acc.w = fmaxf(acc.w + bb.w, 0.f);
        *(float4*)&g_buf2[(size_t)d * 256 + c * 4] = acc;
    } else {
        uint2 hi, lo;
        split_f4(acc, hi, lo);
        ((uint2*)g_g_hi)[(size_t)d * 64 + c] = hi;
        ((uint2*)g_g_lo)[(size_t)d * 64 + c] = lo;
    }
}

// ---------------- launch ----------------------------------------------------
extern "C" void kernel_launch(void* const* d_in, const int* in_sizes, int n_in,
                              void* d_out, int out_size) {
    const float* x   = (const float*)d_in[0];
    const int*   ei  = (const int*)d_in[1];
    const float* W1  = (const float*)d_in[2];
    const float* b1  = (const float*)d_in[3];
    const float* Wmu = (const float*)d_in[4];
    const float* bmu = (const float*)d_in[5];
    const float* Wls = (const float*)d_in[6];
    const float* bls = (const float*)d_in[7];
    float* out = (float*)d_out;

    int N = in_sizes[0] / 512;   // 50000
    int E = in_sizes[1] / 2;     // 800000
    int mt = (N + 127) / 128;

    static cudaStream_t sB = nullptr;
    static cudaEvent_t evFork = nullptr, evJoin = nullptr, evW = nullptr;
    if (sB == nullptr) {
        cudaStreamCreateWithFlags(&sB, cudaStreamNonBlocking);
        cudaEventCreateWithFlags(&evFork, cudaEventDisableTiming);
        cudaEventCreateWithFlags(&evJoin, cudaEventDisableTiming);
        cudaEventCreateWithFlags(&evW, cudaEventDisableTiming);
    }

    // fork: side stream handles CSR build + layer-2 weight prep, overlapping GEMM1
    cudaEventRecord(evFork, 0);
    cudaStreamWaitEvent(sB, evFork, 0);

    k_prep_w1t<<<(256 * 512 + 255) / 256, 256>>>(W1);                    // s0
    k_init_deg<<<(N + 255) / 256, 256, 0, sB>>>(N);                      // sB
    k_hist<<<(E + 255) / 256, 256, 0, sB>>>(ei, E, N);                   // sB
    // layer 1 GEMM (submitted 4th so the profiler window lands on it)
    k_gemm_mma<512, 1><<<dim3(2, mt), 256>>>(x, nullptr, N);             // s0
    k_scanfin<<<1, 1024, 0, sB>>>(N);                                    // sB
    k_fill<<<(E + 255) / 256, 256, 0, sB>>>(ei, E, N);                   // sB
    cudaEventRecord(evJoin, sB);
    k_prep_wct<<<(256 * 256 + 255) / 256, 256, 0, sB>>>(Wmu, Wls, bmu, bls);  // sB
    cudaEventRecord(evW, sB);

    // join: aggregation needs GEMM1 (s0 order) + CSR/dinv (evJoin)
    cudaStreamWaitEvent(0, evJoin, 0);
    k_agg<1><<<N, 64>>>(b1, N);
    k_agg<2><<<N, 64>>>(nullptr, N);
    cudaStreamWaitEvent(0, evW, 0);
    k_gemm_mma<256, 2><<<dim3(2, mt), 256>>>(nullptr, out, N);
}